// round 4
// baseline (speedup 1.0000x reference)
#include <cuda_runtime.h>
#include <cstdint>
#include <cstddef>

#define VSZ 32000
#define TT 64
#define BB 32
#define HH 32
#define EE 200
#define NT (BB*TT)             // 2048 tasks
#define NVC 128                // vocab cols staged per block
#define NCH (VSZ/NVC)          // 250 chunks (grid.y)
#define TG 4                   // task groups per block (128 tasks)
#define NWCH (VSZ/32)          // 1000 per-warp vocab chunks (partials)
#define LOG2E 1.4426950408889634f

// ---------------- scratch ----------------
__device__ float g_xproj[NT*HH];
__device__ float g_H[NT*HH];
__device__ float g_Spart[NWCH*NT];
__device__ float g_C[NT];
__device__ float g_Mpart[NWCH*NT];
__device__ int   g_Ipart[NWCH*NT];

// ---------------- f32x2 helpers ----------------
__device__ __forceinline__ unsigned long long ffma2(unsigned long long a, unsigned long long b, unsigned long long c){
    unsigned long long d;
    asm("fma.rn.f32x2 %0, %1, %2, %3;" : "=l"(d) : "l"(a), "l"(b), "l"(c));
    return d;
}
__device__ __forceinline__ unsigned long long fadd2(unsigned long long a, unsigned long long b){
    unsigned long long d;
    asm("add.rn.f32x2 %0, %1, %2;" : "=l"(d) : "l"(a), "l"(b));
    return d;
}
__device__ __forceinline__ unsigned long long splat2(float x){
    unsigned long long d;
    asm("mov.b64 %0, {%1, %1};" : "=l"(d) : "f"(x));
    return d;
}
__device__ __forceinline__ void unpk(unsigned long long a, float& lo, float& hi){
    asm("mov.b64 {%0, %1}, %2;" : "=f"(lo), "=f"(hi) : "l"(a));
}
__device__ __forceinline__ float ex2a(float x){
    float r; asm("ex2.approx.f32 %0, %1;" : "=f"(r) : "f"(x)); return r;
}
__device__ __forceinline__ float tanh_acc(float x){
    float t = expf(2.0f * x);
    return (t - 1.0f) / (t + 1.0f);
}

// ---------------- K1: xproj ----------------
__global__ void k_xproj(const int* __restrict__ y, const float* __restrict__ emb,
                        const float* __restrict__ Wi, const float* __restrict__ bi,
                        const float* __restrict__ bh){
    int task = blockIdx.x * 8 + (threadIdx.x >> 5);
    int j = threadIdx.x & 31;
    int yv = y[task];
    const float4* er = (const float4*)(emb + (size_t)yv * EE);
    const float4* wr = (const float4*)(Wi + (size_t)j * EE);
    float a0 = 0.f, a1 = 0.f, a2 = 0.f, a3 = 0.f;
#pragma unroll 10
    for (int i = 0; i < EE/4; i++){
        float4 e = er[i]; float4 w = wr[i];
        a0 += e.x * w.x; a1 += e.y * w.y; a2 += e.z * w.z; a3 += e.w * w.w;
    }
    g_xproj[task*HH + j] = (a0 + a1) + (a2 + a3) + bi[j] + bh[j];
}

// ---------------- K2: recurrence (one warp per batch) ----------------
__global__ void k_hchain(const float* __restrict__ enc, const float* __restrict__ Wh){
    int b = blockIdx.x;
    int j = threadIdx.x;
    float wh[HH];
#pragma unroll
    for (int k = 0; k < HH; k++) wh[k] = Wh[j*HH + k];
    __shared__ float hs[HH];
    hs[j] = enc[b*HH + j];
    __syncwarp();
    for (int t = 0; t < TT; t++){
        int row = b*TT + t;
        float a0 = g_xproj[row*HH + j], a1 = 0.f, a2 = 0.f, a3 = 0.f;
#pragma unroll
        for (int k = 0; k < HH; k += 4){
            a0 += wh[k]   * hs[k];
            a1 += wh[k+1] * hs[k+1];
            a2 += wh[k+2] * hs[k+2];
            a3 += wh[k+3] * hs[k+3];
        }
        float h = tanh_acc((a0 + a1) + (a2 + a3));
        __syncwarp();
        hs[j] = h;
        g_H[row*HH + j] = h;
        __syncwarp();
    }
}

// ---- shared staging: Wo chunk TRANSPOSED into sW[k][v] (v contiguous) ----
__device__ __forceinline__ void stage_chunk(float* sW, float* sbo,
                                            const float* __restrict__ Wo,
                                            const float* __restrict__ bo,
                                            int v0, int tid, float bscale){
    // 128 threads, one Wo row each; STS conflict-free (lanes -> consecutive v)
    const float4* src = (const float4*)(Wo + (size_t)(v0 + tid) * HH);
#pragma unroll
    for (int j = 0; j < 8; j++){
        float4 w = src[j];
        sW[(4*j+0)*NVC + tid] = w.x;
        sW[(4*j+1)*NVC + tid] = w.y;
        sW[(4*j+2)*NVC + tid] = w.z;
        sW[(4*j+3)*NVC + tid] = w.w;
    }
    sbo[tid] = bo[v0 + tid] * bscale;
}

// ---------------- K3a: pass1 — sum of exp per (task, 32-v warp chunk) ----------------
__global__ void __launch_bounds__(128) k_pass1(const float* __restrict__ Wo,
                                               const float* __restrict__ bo){
    __shared__ float sW[HH*NVC];
    __shared__ float sbo[NVC];
    int tid = threadIdx.x;
    int w = tid >> 5, lane = tid & 31;
    int v0 = blockIdx.y * NVC;
    stage_chunk(sW, sbo, Wo, bo, v0, tid, LOG2E);   // bo pre-scaled: work in log2 units
    __syncthreads();

    const float* sWw = sW + w*32;        // this warp's 32 vocab columns
    int c = blockIdx.y*4 + w;            // global 32-v chunk id (v = c*32 ...)

#pragma unroll 1
    for (int g = 0; g < TG; g++){
        int task = blockIdx.x*(32*TG) + g*32 + lane;
        // h row (pre-scaled by log2e) in registers
        float h[HH];
        {
            const float4* hp = (const float4*)(g_H + (size_t)task * HH);
#pragma unroll
            for (int i = 0; i < 8; i++){
                float4 x = hp[i];
                h[4*i] = x.x*LOG2E; h[4*i+1] = x.y*LOG2E; h[4*i+2] = x.z*LOG2E; h[4*i+3] = x.w*LOG2E;
            }
        }
        // accumulators = 32 logits (log2 units), init = bo*log2e
        unsigned long long acc[16];
        {
            const ulonglong2* bp = (const ulonglong2*)(sbo + w*32);
#pragma unroll
            for (int j = 0; j < 8; j++){ ulonglong2 b2 = bp[j]; acc[2*j] = b2.x; acc[2*j+1] = b2.y; }
        }
#pragma unroll
        for (int k = 0; k < HH; k++){
            unsigned long long hk = splat2(h[k]);
            const ulonglong2* wp = (const ulonglong2*)(sWw + k*NVC);
#pragma unroll
            for (int j = 0; j < 8; j++){
                ulonglong2 wv = wp[j];
                acc[2*j]   = ffma2(hk, wv.x, acc[2*j]);
                acc[2*j+1] = ffma2(hk, wv.y, acc[2*j+1]);
            }
        }
        float s = 0.f;
#pragma unroll
        for (int i = 0; i < 16; i++){
            float l0, l1; unpk(acc[i], l0, l1);
            s += ex2a(l0); s += ex2a(l1);
        }
        g_Spart[(size_t)c*NT + task] = s;
    }
}

// ---------------- K4: C[task] = log(sum of 1000 partials) ----------------
__global__ void k_lse(){
    __shared__ float ps[8][32];
    int lane = threadIdx.x & 31, sl = threadIdx.x >> 5;
    int task = blockIdx.x*32 + lane;
    float s = 0.f;
    int c0 = sl*125;
#pragma unroll 5
    for (int c = c0; c < c0+125; c++) s += g_Spart[(size_t)c*NT + task];
    ps[sl][lane] = s;
    __syncthreads();
    if (sl == 0){
        float t = 0.f;
#pragma unroll
        for (int i = 0; i < 8; i++) t += ps[i][lane];
        g_C[task] = logf(t);
    }
}

// ---------------- K3b: pass2 — logprob write + argmax partials ----------------
__global__ void __launch_bounds__(128) k_pass2(const float* __restrict__ Wo,
                                               const float* __restrict__ bo,
                                               float* __restrict__ out){
    __shared__ float sW[HH*NVC];
    __shared__ float sbo[NVC];
    __shared__ float tile[4][32*33];
    int tid = threadIdx.x;
    int w = tid >> 5, lane = tid & 31;
    int v0 = blockIdx.y * NVC;
    stage_chunk(sW, sbo, Wo, bo, v0, tid, 1.0f);
    __syncthreads();

    const float* sWw = sW + w*32;
    int c = blockIdx.y*4 + w;
    int vbase = c*32;
    float* tw = tile[w];

#pragma unroll 1
    for (int g = 0; g < TG; g++){
        int task = blockIdx.x*(32*TG) + g*32 + lane;
        float h[HH];
        {
            const float4* hp = (const float4*)(g_H + (size_t)task * HH);
#pragma unroll
            for (int i = 0; i < 8; i++){
                float4 x = hp[i];
                h[4*i] = x.x; h[4*i+1] = x.y; h[4*i+2] = x.z; h[4*i+3] = x.w;
            }
        }
        unsigned long long negC = splat2(-g_C[task]);
        unsigned long long acc[16];
        {
            const ulonglong2* bp = (const ulonglong2*)(sbo + w*32);
#pragma unroll
            for (int j = 0; j < 8; j++){
                ulonglong2 b2 = bp[j];
                acc[2*j]   = fadd2(b2.x, negC);   // fold (bo - C) into init
                acc[2*j+1] = fadd2(b2.y, negC);
            }
        }
#pragma unroll
        for (int k = 0; k < HH; k++){
            unsigned long long hk = splat2(h[k]);
            const ulonglong2* wp = (const ulonglong2*)(sWw + k*NVC);
#pragma unroll
            for (int j = 0; j < 8; j++){
                ulonglong2 wv = wp[j];
                acc[2*j]   = ffma2(hk, wv.x, acc[2*j]);
                acc[2*j+1] = ffma2(hk, wv.y, acc[2*j+1]);
            }
        }
        // epilogue: smem transpose + per-lane argmax (ascending v, strict > => first max wins)
        float mx = -3.4e38f; int mi = 0;
#pragma unroll
        for (int i = 0; i < 16; i++){
            float l0, l1; unpk(acc[i], l0, l1);
            tw[lane*33 + 2*i]   = l0;
            tw[lane*33 + 2*i+1] = l1;
            if (l0 > mx){ mx = l0; mi = 2*i;   }
            if (l1 > mx){ mx = l1; mi = 2*i+1; }
        }
        __syncwarp();
        // coalesced flush: row r = one task, 32 consecutive v
        float* ob = out + (size_t)(blockIdx.x*(32*TG) + g*32) * VSZ + vbase + lane;
#pragma unroll 8
        for (int r = 0; r < 32; r++){
            ob[(size_t)r * VSZ] = tw[r*33 + lane];
        }
        __syncwarp();
        g_Mpart[(size_t)c*NT + task] = mx;
        g_Ipart[(size_t)c*NT + task] = vbase + mi;
    }
}

// ---------------- K5: final argmax over 1000 chunk partials ----------------
__global__ void k_argmax(float* __restrict__ preds){
    __shared__ float pm[8][32];
    __shared__ int   pi[8][32];
    int lane = threadIdx.x & 31, sl = threadIdx.x >> 5;
    int task = blockIdx.x*32 + lane;
    float mx = -3.4e38f; int mi = 0;
    int c0 = sl*125;
    for (int cc = c0; cc < c0+125; cc++){            // ascending c => ascending v
        float m = g_Mpart[(size_t)cc*NT + task];
        if (m > mx){ mx = m; mi = g_Ipart[(size_t)cc*NT + task]; }
    }
    pm[sl][lane] = mx; pi[sl][lane] = mi;
    __syncthreads();
    if (sl == 0){
        float M = -3.4e38f; int I = 0;
#pragma unroll
        for (int s = 0; s < 8; s++){                 // ascending slice => ascending v
            float m = pm[s][lane];
            if (m > M){ M = m; I = pi[s][lane]; }
        }
        preds[task] = (float)I;
    }
}

// ---------------- launch ----------------
extern "C" void kernel_launch(void* const* d_in, const int* in_sizes, int n_in,
                              void* d_out, int out_size){
    const int*   y   = (const int*)  d_in[0];
    const float* enc = (const float*)d_in[1];
    const float* emb = (const float*)d_in[2];
    const float* Wi  = (const float*)d_in[3];
    const float* bi  = (const float*)d_in[4];
    const float* Wh  = (const float*)d_in[5];
    const float* bh  = (const float*)d_in[6];
    const float* Wo  = (const float*)d_in[7];
    const float* bo  = (const float*)d_in[8];
    float* out = (float*)d_out;

    k_xproj<<<NT/8, 256>>>(y, emb, Wi, bi, bh);
    k_hchain<<<BB, 32>>>(enc, Wh);
    k_pass1<<<dim3(NT/(32*TG), NCH), 128>>>(Wo, bo);
    k_lse<<<NT/32, 256>>>();
    k_pass2<<<dim3(NT/(32*TG), NCH), 128>>>(Wo, bo, out);
    if ((long long)out_size > (long long)NT * VSZ){
        k_argmax<<<NT/32, 256>>>(out + (size_t)NT * VSZ);
    }
}

// round 5
// speedup vs baseline: 5.3959x; 5.3959x over previous
#include <cuda_runtime.h>
#include <cstdint>
#include <cstddef>

#define VSZ 32000
#define TT 64
#define BB 32
#define HH 32
#define EE 200
#define NT (BB*TT)            // 2048 tasks
#define VB 256                // vocab per block
#define NCHB (VSZ/VB)         // 125 vocab chunks
#define RT 8                  // tasks per thread
#define TB 64                 // tasks per block (8 warps * 8)
#define LOG2E 1.4426950408889634f

// ---------------- scratch ----------------
__device__ float g_xproj[NT*HH];
__device__ float g_H[NT*HH];
__device__ float g_Spart[NCHB*NT];
__device__ float g_C[NT];
__device__ float g_Mpart[NCHB*NT];
__device__ int   g_Ipart[NCHB*NT];

typedef unsigned long long ull;

// ---------------- f32x2 helpers ----------------
__device__ __forceinline__ ull ffma2(ull a, ull b, ull c){
    ull d; asm("fma.rn.f32x2 %0, %1, %2, %3;" : "=l"(d) : "l"(a), "l"(b), "l"(c)); return d;
}
__device__ __forceinline__ ull fadd2(ull a, ull b){
    ull d; asm("add.rn.f32x2 %0, %1, %2;" : "=l"(d) : "l"(a), "l"(b)); return d;
}
__device__ __forceinline__ ull splat2(float x){
    ull d; asm("mov.b64 %0, {%1, %1};" : "=l"(d) : "f"(x)); return d;
}
__device__ __forceinline__ void unpk(ull a, float& lo, float& hi){
    asm("mov.b64 {%0, %1}, %2;" : "=f"(lo), "=f"(hi) : "l"(a));
}
__device__ __forceinline__ float ex2a(float x){
    float r; asm("ex2.approx.f32 %0, %1;" : "=f"(r) : "f"(x)); return r;
}
__device__ __forceinline__ float tanh_acc(float x){
    float t = expf(2.0f * x);
    return (t - 1.0f) / (t + 1.0f);
}

// ---------------- K1: xproj ----------------
__global__ void k_xproj(const int* __restrict__ y, const float* __restrict__ emb,
                        const float* __restrict__ Wi, const float* __restrict__ bi,
                        const float* __restrict__ bh){
    int task = blockIdx.x * 8 + (threadIdx.x >> 5);
    int j = threadIdx.x & 31;
    int yv = y[task];
    const float4* er = (const float4*)(emb + (size_t)yv * EE);
    const float4* wr = (const float4*)(Wi + (size_t)j * EE);
    float a0 = 0.f, a1 = 0.f, a2 = 0.f, a3 = 0.f;
#pragma unroll 10
    for (int i = 0; i < EE/4; i++){
        float4 e = er[i]; float4 w = wr[i];
        a0 += e.x * w.x; a1 += e.y * w.y; a2 += e.z * w.z; a3 += e.w * w.w;
    }
    g_xproj[task*HH + j] = (a0 + a1) + (a2 + a3) + bi[j] + bh[j];
}

// ---------------- K2: recurrence (one warp per batch) ----------------
__global__ void k_hchain(const float* __restrict__ enc, const float* __restrict__ Wh){
    int b = blockIdx.x;
    int j = threadIdx.x;
    float wh[HH];
#pragma unroll
    for (int k = 0; k < HH; k++) wh[k] = Wh[j*HH + k];
    __shared__ float hs[HH];
    hs[j] = enc[b*HH + j];
    __syncwarp();
    for (int t = 0; t < TT; t++){
        int row = b*TT + t;
        float a0 = g_xproj[row*HH + j], a1 = 0.f, a2 = 0.f, a3 = 0.f;
#pragma unroll
        for (int k = 0; k < HH; k += 4){
            a0 += wh[k]   * hs[k];
            a1 += wh[k+1] * hs[k+1];
            a2 += wh[k+2] * hs[k+2];
            a3 += wh[k+3] * hs[k+3];
        }
        float h = tanh_acc((a0 + a1) + (a2 + a3));
        __syncwarp();
        hs[j] = h;
        g_H[row*HH + j] = h;
        __syncwarp();
    }
}

// ---- shared staging for the tiled GEMM kernels ----
// sWf: Wo chunk, pre-paired layout: ull index (k*4+j)*32 + m holds {Wo[vb+m*8+2j][k], Wo[vb+m*8+2j+1][k]}
// sBf: bo pairs:                    ull index j*32 + m     holds {bo[vb+m*8+2j],     bo[vb+m*8+2j+1]}
// sH : h rows for the block's TB tasks, [task][k]
__device__ __forceinline__ void stage_gemm(float* sWf, float* sBf, float* sH,
                                           const float* __restrict__ Wo,
                                           const float* __restrict__ bo,
                                           int vb, int task0, int tid){
    int m = tid >> 3, j = (tid >> 1) & 3, half = tid & 1;
    const float4* src = (const float4*)(Wo + (size_t)(vb + tid) * HH);
#pragma unroll
    for (int q = 0; q < 8; q++){
        float4 w = src[q];
        sWf[((4*q+0)*4 + j)*64 + m*2 + half] = w.x;
        sWf[((4*q+1)*4 + j)*64 + m*2 + half] = w.y;
        sWf[((4*q+2)*4 + j)*64 + m*2 + half] = w.z;
        sWf[((4*q+3)*4 + j)*64 + m*2 + half] = w.w;
    }
    sBf[(j*32 + m)*2 + half] = bo[vb + tid];
    const float4* hsrc = (const float4*)(g_H + (size_t)task0 * HH);
    float4* hdst = (float4*)sH;
#pragma unroll
    for (int q = tid; q < TB*HH/4; q += 256) hdst[q] = hsrc[q];
}

// ---------------- K3: gemm1 — expsum partials per (task, 256-v chunk) ----------------
__global__ void __launch_bounds__(256) k_gemm1(const float* __restrict__ Wo,
                                               const float* __restrict__ bo){
    __shared__ float sWf[HH*VB];     // 32 KB
    __shared__ float sBf[VB];        // 1 KB
    __shared__ float sH[TB*HH];      // 8 KB
    int tid = threadIdx.x;
    int wrp = tid >> 5, lane = tid & 31;
    int vb = blockIdx.y * VB;
    int task0 = blockIdx.x * TB;
    stage_gemm(sWf, sBf, sH, Wo, bo, vb, task0, tid);
    __syncthreads();

    const ull* wp = (const ull*)sWf;
    const ull* bp = (const ull*)sBf;
    const float* hp = sH + (wrp*RT)*HH;

    ull acc[RT][4];
#pragma unroll
    for (int i = 0; i < RT; i++)
#pragma unroll
        for (int j = 0; j < 4; j++) acc[i][j] = bp[j*32 + lane];

#pragma unroll 8
    for (int k = 0; k < HH; k++){
        ull w2[4];
#pragma unroll
        for (int j = 0; j < 4; j++) w2[j] = wp[(k*4 + j)*32 + lane];
#pragma unroll
        for (int i = 0; i < RT; i++){
            ull h2 = splat2(hp[i*HH + k]);
#pragma unroll
            for (int j = 0; j < 4; j++) acc[i][j] = ffma2(h2, w2[j], acc[i][j]);
        }
    }

    int cy = blockIdx.y;
#pragma unroll
    for (int i = 0; i < RT; i++){
        float s = 0.f;
#pragma unroll
        for (int j = 0; j < 4; j++){
            float a, b; unpk(acc[i][j], a, b);
            s += ex2a(a * LOG2E);
            s += ex2a(b * LOG2E);
        }
#pragma unroll
        for (int o = 16; o; o >>= 1) s += __shfl_xor_sync(0xffffffffu, s, o);
        if (lane == 0) g_Spart[(size_t)cy*NT + task0 + wrp*RT + i] = s;
    }
}

// ---------------- K4: C[task] = log(sum of 125 partials) ----------------
__global__ void k_lse(){
    int task = blockIdx.x * 256 + threadIdx.x;
    float s0 = 0.f, s1 = 0.f, s2 = 0.f, s3 = 0.f, s4 = 0.f;
#pragma unroll 5
    for (int c = 0; c < NCHB; c += 5){
        s0 += g_Spart[(size_t)(c  )*NT + task];
        s1 += g_Spart[(size_t)(c+1)*NT + task];
        s2 += g_Spart[(size_t)(c+2)*NT + task];
        s3 += g_Spart[(size_t)(c+3)*NT + task];
        s4 += g_Spart[(size_t)(c+4)*NT + task];
    }
    g_C[task] = logf(((s0 + s1) + (s2 + s3)) + s4);
}

// ---------------- K5: gemm2 — write logprobs + argmax partials ----------------
__global__ void __launch_bounds__(256) k_gemm2(const float* __restrict__ Wo,
                                               const float* __restrict__ bo,
                                               float* __restrict__ out){
    __shared__ float sWf[HH*VB];
    __shared__ float sBf[VB];
    __shared__ float sH[TB*HH];
    int tid = threadIdx.x;
    int wrp = tid >> 5, lane = tid & 31;
    int vb = blockIdx.y * VB;
    int task0 = blockIdx.x * TB;
    stage_gemm(sWf, sBf, sH, Wo, bo, vb, task0, tid);
    __syncthreads();

    const ull* wp = (const ull*)sWf;
    const ull* bp = (const ull*)sBf;
    const float* hp = sH + (wrp*RT)*HH;

    ull acc[RT][4];
#pragma unroll
    for (int i = 0; i < RT; i++){
        ull nc = splat2(-g_C[task0 + wrp*RT + i]);
#pragma unroll
        for (int j = 0; j < 4; j++) acc[i][j] = fadd2(bp[j*32 + lane], nc);
    }

#pragma unroll 8
    for (int k = 0; k < HH; k++){
        ull w2[4];
#pragma unroll
        for (int j = 0; j < 4; j++) w2[j] = wp[(k*4 + j)*32 + lane];
#pragma unroll
        for (int i = 0; i < RT; i++){
            ull h2 = splat2(hp[i*HH + k]);
#pragma unroll
            for (int j = 0; j < 4; j++) acc[i][j] = ffma2(h2, w2[j], acc[i][j]);
        }
    }

    int cy = blockIdx.y;
#pragma unroll
    for (int i = 0; i < RT; i++){
        int task = task0 + wrp*RT + i;
        float4 o1, o2;
        unpk(acc[i][0], o1.x, o1.y); unpk(acc[i][1], o1.z, o1.w);
        unpk(acc[i][2], o2.x, o2.y); unpk(acc[i][3], o2.z, o2.w);
        float* op = out + (size_t)task * VSZ + vb + lane*8;
        *(float4*)op       = o1;
        *(float4*)(op + 4) = o2;
        // per-lane argmax over its 8 v, ascending order, strict > (first max wins)
        float mx = o1.x; int mi = lane*8;
        if (o1.y > mx){ mx = o1.y; mi = lane*8 + 1; }
        if (o1.z > mx){ mx = o1.z; mi = lane*8 + 2; }
        if (o1.w > mx){ mx = o1.w; mi = lane*8 + 3; }
        if (o2.x > mx){ mx = o2.x; mi = lane*8 + 4; }
        if (o2.y > mx){ mx = o2.y; mi = lane*8 + 5; }
        if (o2.z > mx){ mx = o2.z; mi = lane*8 + 6; }
        if (o2.w > mx){ mx = o2.w; mi = lane*8 + 7; }
        // butterfly combine with tie -> smaller index (exact first-occurrence argmax)
#pragma unroll
        for (int o = 16; o; o >>= 1){
            float om = __shfl_xor_sync(0xffffffffu, mx, o);
            int   oi = __shfl_xor_sync(0xffffffffu, mi, o);
            if (om > mx || (om == mx && oi < mi)){ mx = om; mi = oi; }
        }
        if (lane == 0){
            g_Mpart[(size_t)cy*NT + task] = mx;
            g_Ipart[(size_t)cy*NT + task] = vb + mi;
        }
    }
}

// ---------------- K6: combine argmax partials (ascending chunk, strict >) ----------------
__global__ void k_argmax(float* __restrict__ preds){
    int task = blockIdx.x * 256 + threadIdx.x;
    float mx = -3.4e38f; int mi = 0;
    for (int c = 0; c < NCHB; c++){
        float m = g_Mpart[(size_t)c*NT + task];
        int   i = g_Ipart[(size_t)c*NT + task];
        if (m > mx){ mx = m; mi = i; }
    }
    preds[task] = (float)mi;
}

// ---------------- launch ----------------
extern "C" void kernel_launch(void* const* d_in, const int* in_sizes, int n_in,
                              void* d_out, int out_size){
    const int*   y   = (const int*)  d_in[0];
    const float* enc = (const float*)d_in[1];
    const float* emb = (const float*)d_in[2];
    const float* Wi  = (const float*)d_in[3];
    const float* bi  = (const float*)d_in[4];
    const float* Wh  = (const float*)d_in[5];
    const float* bh  = (const float*)d_in[6];
    const float* Wo  = (const float*)d_in[7];
    const float* bo  = (const float*)d_in[8];
    float* out = (float*)d_out;

    k_xproj<<<NT/8, 256>>>(y, emb, Wi, bi, bh);
    k_hchain<<<BB, 32>>>(enc, Wh);
    k_gemm1<<<dim3(NT/TB, NCHB), 256>>>(Wo, bo);
    k_lse<<<NT/256, 256>>>();
    k_gemm2<<<dim3(NT/TB, NCHB), 256>>>(Wo, bo, out);
    if ((long long)out_size > (long long)NT * VSZ){
        k_argmax<<<NT/256, 256>>>(out + (size_t)NT * VSZ);
    }
}

// round 6
// speedup vs baseline: 5.8852x; 1.0907x over previous
#include <cuda_runtime.h>
#include <cstdint>
#include <cstddef>

#define VSZ 32000
#define TT 64
#define BB 32
#define HH 32
#define EE 200
#define NT (BB*TT)            // 2048 tasks
#define VB 256                // vocab per block
#define NCHB (VSZ/VB)         // 125 vocab chunks
#define RT 8                  // tasks per thread
#define TB 64                 // tasks per block (8 warps * 8)
#define LOG2E 1.4426950408889634f

// ---------------- scratch ----------------
__device__ float g_xproj[NT*HH];
__device__ float g_H[NT*HH];
__device__ float g_Spart[NCHB*NT];
__device__ float g_C[NT];
__device__ float g_Mpart[NCHB*NT];
__device__ int   g_Ipart[NCHB*NT];

typedef unsigned long long ull;

// ---------------- f32x2 helpers ----------------
__device__ __forceinline__ ull ffma2(ull a, ull b, ull c){
    ull d; asm("fma.rn.f32x2 %0, %1, %2, %3;" : "=l"(d) : "l"(a), "l"(b), "l"(c)); return d;
}
__device__ __forceinline__ ull splat2(float x){
    ull d; asm("mov.b64 %0, {%1, %1};" : "=l"(d) : "f"(x)); return d;
}
__device__ __forceinline__ void unpk(ull a, float& lo, float& hi){
    asm("mov.b64 {%0, %1}, %2;" : "=f"(lo), "=f"(hi) : "l"(a));
}
__device__ __forceinline__ float ex2a(float x){
    float r; asm("ex2.approx.f32 %0, %1;" : "=f"(r) : "f"(x)); return r;
}
__device__ __forceinline__ float tanh_acc(float x){
    float t = expf(2.0f * x);
    return (t - 1.0f) / (t + 1.0f);
}

// ---------------- K1: xproj ----------------
__global__ void k_xproj(const int* __restrict__ y, const float* __restrict__ emb,
                        const float* __restrict__ Wi, const float* __restrict__ bi,
                        const float* __restrict__ bh){
    int task = blockIdx.x * 8 + (threadIdx.x >> 5);
    int j = threadIdx.x & 31;
    int yv = y[task];
    const float4* er = (const float4*)(emb + (size_t)yv * EE);
    const float4* wr = (const float4*)(Wi + (size_t)j * EE);
    float a0 = 0.f, a1 = 0.f, a2 = 0.f, a3 = 0.f;
#pragma unroll 10
    for (int i = 0; i < EE/4; i++){
        float4 e = er[i]; float4 w = wr[i];
        a0 += e.x * w.x; a1 += e.y * w.y; a2 += e.z * w.z; a3 += e.w * w.w;
    }
    g_xproj[task*HH + j] = (a0 + a1) + (a2 + a3) + bi[j] + bh[j];
}

// ---------------- K2: recurrence (one warp per batch) ----------------
__global__ void k_hchain(const float* __restrict__ enc, const float* __restrict__ Wh){
    int b = blockIdx.x;
    int j = threadIdx.x;
    float wh[HH];
#pragma unroll
    for (int k = 0; k < HH; k++) wh[k] = Wh[j*HH + k];
    __shared__ float hs[HH];
    hs[j] = enc[b*HH + j];
    __syncwarp();
    for (int t = 0; t < TT; t++){
        int row = b*TT + t;
        float a0 = g_xproj[row*HH + j], a1 = 0.f, a2 = 0.f, a3 = 0.f;
#pragma unroll
        for (int k = 0; k < HH; k += 4){
            a0 += wh[k]   * hs[k];
            a1 += wh[k+1] * hs[k+1];
            a2 += wh[k+2] * hs[k+2];
            a3 += wh[k+3] * hs[k+3];
        }
        float h = tanh_acc((a0 + a1) + (a2 + a3));
        __syncwarp();
        hs[j] = h;
        g_H[row*HH + j] = h;
        __syncwarp();
    }
}

// ---- staging: Wo chunk pre-paired; bo pairs; h rows pre-DUPLICATED as {h,h} ----
// sWf ull index (k*4+j)*32 + m : {Wo[vb+m*8+2j][k], Wo[vb+m*8+2j+1][k]}
// sBf ull index  j*32 + m      : {bo[vb+m*8+2j],    bo[vb+m*8+2j+1]}
// sH2 ull index  t*HH + k      : {h[task0+t][k], h[task0+t][k]}
__device__ __forceinline__ void stage_gemm(float* sWf, float* sBf, ull* sH2,
                                           const float* __restrict__ Wo,
                                           const float* __restrict__ bo,
                                           int vb, int task0, int tid){
    int m = tid >> 3, j = (tid >> 1) & 3, half = tid & 1;
    const float4* src = (const float4*)(Wo + (size_t)(vb + tid) * HH);
#pragma unroll
    for (int q = 0; q < 8; q++){
        float4 w = src[q];
        sWf[((4*q+0)*4 + j)*64 + m*2 + half] = w.x;
        sWf[((4*q+1)*4 + j)*64 + m*2 + half] = w.y;
        sWf[((4*q+2)*4 + j)*64 + m*2 + half] = w.z;
        sWf[((4*q+3)*4 + j)*64 + m*2 + half] = w.w;
    }
    sBf[(j*32 + m)*2 + half] = bo[vb + tid];
    const float* hsrc = g_H + (size_t)task0 * HH;
#pragma unroll
    for (int q = tid; q < TB*HH; q += 256) sH2[q] = splat2(hsrc[q]);
}

// ---------------- K3: fused GEMM — raw logits to out + expsum & argmax partials ----------------
__global__ void __launch_bounds__(256) k_gemm_fused(const float* __restrict__ Wo,
                                                    const float* __restrict__ bo,
                                                    float* __restrict__ out){
    __shared__ float sWf[HH*VB];     // 32 KB
    __shared__ float sBf[VB];        // 1 KB
    __shared__ ull   sH2[TB*HH];     // 16 KB (duplicated h pairs)
    int tid = threadIdx.x;
    int wrp = tid >> 5, lane = tid & 31;
    int vb = blockIdx.y * VB;
    int task0 = blockIdx.x * TB;
    stage_gemm(sWf, sBf, sH2, Wo, bo, vb, task0, tid);
    __syncthreads();

    const ull* wp = (const ull*)sWf;
    const ull* bp = (const ull*)sBf;
    const ull* hp = sH2 + (wrp*RT)*HH;

    ull acc[RT][4];
#pragma unroll
    for (int i = 0; i < RT; i++)
#pragma unroll
        for (int j = 0; j < 4; j++) acc[i][j] = bp[j*32 + lane];

#pragma unroll 4
    for (int k = 0; k < HH; k++){
        ull w2[4];
#pragma unroll
        for (int j = 0; j < 4; j++) w2[j] = wp[(k*4 + j)*32 + lane];
#pragma unroll
        for (int i = 0; i < RT; i++){
            ull h2 = hp[i*HH + k];              // broadcast LDS.64, no splat mov
#pragma unroll
            for (int j = 0; j < 4; j++) acc[i][j] = ffma2(h2, w2[j], acc[i][j]);
        }
    }

    int cy = blockIdx.y;
#pragma unroll
    for (int i = 0; i < RT; i++){
        int task = task0 + wrp*RT + i;
        float4 o1, o2;
        unpk(acc[i][0], o1.x, o1.y); unpk(acc[i][1], o1.z, o1.w);
        unpk(acc[i][2], o2.x, o2.y); unpk(acc[i][3], o2.z, o2.w);
        // raw logits -> out (k_fix subtracts C later)
        float* op = out + (size_t)task * VSZ + vb + lane*8;
        *(float4*)op       = o1;
        *(float4*)(op + 4) = o2;
        // expsum over the 8 logits
        float s = ex2a(o1.x*LOG2E) + ex2a(o1.y*LOG2E) + ex2a(o1.z*LOG2E) + ex2a(o1.w*LOG2E)
                + ex2a(o2.x*LOG2E) + ex2a(o2.y*LOG2E) + ex2a(o2.z*LOG2E) + ex2a(o2.w*LOG2E);
#pragma unroll
        for (int o = 16; o; o >>= 1) s += __shfl_xor_sync(0xffffffffu, s, o);
        // per-lane argmax (ascending v, strict > => first occurrence)
        float mx = o1.x; int mi = lane*8;
        if (o1.y > mx){ mx = o1.y; mi = lane*8 + 1; }
        if (o1.z > mx){ mx = o1.z; mi = lane*8 + 2; }
        if (o1.w > mx){ mx = o1.w; mi = lane*8 + 3; }
        if (o2.x > mx){ mx = o2.x; mi = lane*8 + 4; }
        if (o2.y > mx){ mx = o2.y; mi = lane*8 + 5; }
        if (o2.z > mx){ mx = o2.z; mi = lane*8 + 6; }
        if (o2.w > mx){ mx = o2.w; mi = lane*8 + 7; }
#pragma unroll
        for (int o = 16; o; o >>= 1){
            float om = __shfl_xor_sync(0xffffffffu, mx, o);
            int   oi = __shfl_xor_sync(0xffffffffu, mi, o);
            if (om > mx || (om == mx && oi < mi)){ mx = om; mi = oi; }
        }
        if (lane == 0){
            g_Spart[(size_t)cy*NT + task] = s;
            g_Mpart[(size_t)cy*NT + task] = mx;
            g_Ipart[(size_t)cy*NT + task] = vb + mi;
        }
    }
}

// ---------------- K4: C[task] = log(sum of 125 partials), 4-slice parallel ----------------
__global__ void k_lse(){
    __shared__ float ps[4][64];
    int t = threadIdx.x & 63, sl = threadIdx.x >> 6;
    int task = blockIdx.x*64 + t;
    float s = 0.f;
    for (int c = sl; c < NCHB; c += 4) s += g_Spart[(size_t)c*NT + task];
    ps[sl][t] = s;
    __syncthreads();
    if (sl == 0) g_C[task] = logf((ps[0][t] + ps[1][t]) + (ps[2][t] + ps[3][t]));
}

// ---------------- K5: streaming fix-up — out[task][v] -= C[task] ----------------
__global__ void __launch_bounds__(256) k_fix(float* __restrict__ out){
    int task = blockIdx.x;
    float c = g_C[task];
    float4* p = (float4*)(out + (size_t)task * VSZ);
#pragma unroll 4
    for (int i = threadIdx.x; i < VSZ/4; i += 256){
        float4 v = p[i];
        v.x -= c; v.y -= c; v.z -= c; v.w -= c;
        p[i] = v;
    }
}

// ---------------- K6: combine argmax partials, 4-slice + tie->min index ----------------
__global__ void k_argmax(float* __restrict__ preds){
    __shared__ float pm[4][64];
    __shared__ int   pi[4][64];
    int t = threadIdx.x & 63, sl = threadIdx.x >> 6;
    int task = blockIdx.x*64 + t;
    float mx = -3.4e38f; int mi = 0x7fffffff;
    for (int c = sl; c < NCHB; c += 4){      // ascending within slice: strict > keeps min index
        float m = g_Mpart[(size_t)c*NT + task];
        if (m > mx){ mx = m; mi = g_Ipart[(size_t)c*NT + task]; }
    }
    pm[sl][t] = mx; pi[sl][t] = mi;
    __syncthreads();
    if (sl == 0){
        float M = pm[0][t]; int I = pi[0][t];
#pragma unroll
        for (int s = 1; s < 4; s++){
            float m = pm[s][t]; int i = pi[s][t];
            if (m > M || (m == M && i < I)){ M = m; I = i; }   // tie -> min index = first occurrence
        }
        preds[task] = (float)I;
    }
}

// ---------------- launch ----------------
extern "C" void kernel_launch(void* const* d_in, const int* in_sizes, int n_in,
                              void* d_out, int out_size){
    const int*   y   = (const int*)  d_in[0];
    const float* enc = (const float*)d_in[1];
    const float* emb = (const float*)d_in[2];
    const float* Wi  = (const float*)d_in[3];
    const float* bi  = (const float*)d_in[4];
    const float* Wh  = (const float*)d_in[5];
    const float* bh  = (const float*)d_in[6];
    const float* Wo  = (const float*)d_in[7];
    const float* bo  = (const float*)d_in[8];
    float* out = (float*)d_out;

    k_xproj<<<NT/8, 256>>>(y, emb, Wi, bi, bh);
    k_hchain<<<BB, 32>>>(enc, Wh);
    k_gemm_fused<<<dim3(NT/TB, NCHB), 256>>>(Wo, bo, out);
    k_lse<<<NT/64, 256>>>();
    k_fix<<<NT, 256>>>(out);
    if ((long long)out_size > (long long)NT * VSZ){
        k_argmax<<<NT/64, 256>>>(out + (size_t)NT * VSZ);
    }
}